// round 13
// baseline (speedup 1.0000x reference)
#include <cuda_runtime.h>
#include <cuda_bf16.h>
#include <stdint.h>

#define D 128
#define D2 256
#define NMAX 100096
#define EMAX 3205120

// ---------------- scratch (device globals; no allocation) ----------------
__device__ __align__(16) float g_hs [(size_t)NMAX * D];   // h_scaled, later r
__device__ __align__(16) float g_acc[(size_t)NMAX * D];   // g, later y
__device__ __align__(16) float g_z  [(size_t)NMAX * D2];  // FFN hidden
__device__ int   g_ecnt[NMAX];
__device__ int   g_offs[NMAX];
__device__ int   g_cur [NMAX];
__device__ int   g_csr [EMAX];
__device__ int   g_bsum [128];
__device__ int   g_bsumx[128];
__device__ float g_dinv[NMAX];
__device__ float g_sum [3 * D];
__device__ float g_sq  [3 * D];
__device__ float g_scale[3 * D];
__device__ float g_shift[3 * D];

// ---------------- helpers ----------------
__device__ __forceinline__ uint32_t smem_u32(const void* p) {
    uint32_t a;
    asm("{ .reg .u64 t; cvta.to.shared.u64 t, %1; cvt.u32.u64 %0, t; }" : "=r"(a) : "l"(p));
    return a;
}
__device__ __forceinline__ void split2(float a, float b, uint32_t& hi, uint32_t& lo) {
    __nv_bfloat16 ha = __float2bfloat16(a), hb = __float2bfloat16(b);
    float ra = a - __bfloat162float(ha);
    float rb = b - __bfloat162float(hb);
    __nv_bfloat16 la = __float2bfloat16(ra), lb = __float2bfloat16(rb);
    hi = (uint32_t)__bfloat16_as_ushort(ha) | ((uint32_t)__bfloat16_as_ushort(hb) << 16);
    lo = (uint32_t)__bfloat16_as_ushort(la) | ((uint32_t)__bfloat16_as_ushort(lb) << 16);
}
__device__ __forceinline__ void ldsm_x4(uint32_t* r, uint32_t addr) {
    asm volatile("ldmatrix.sync.aligned.m8n8.x4.shared.b16 {%0,%1,%2,%3}, [%4];"
                 : "=r"(r[0]), "=r"(r[1]), "=r"(r[2]), "=r"(r[3]) : "r"(addr));
}
__device__ __forceinline__ void ldsm_x4_t(uint32_t* r, uint32_t addr) {
    asm volatile("ldmatrix.sync.aligned.m8n8.x4.trans.shared.b16 {%0,%1,%2,%3}, [%4];"
                 : "=r"(r[0]), "=r"(r[1]), "=r"(r[2]), "=r"(r[3]) : "r"(addr));
}
__device__ __forceinline__ void mma16816(float* d, const uint32_t* a, uint32_t b0, uint32_t b1) {
    asm volatile(
        "mma.sync.aligned.m16n8k16.row.col.f32.bf16.bf16.f32 "
        "{%0,%1,%2,%3}, {%4,%5,%6,%7}, {%8,%9}, {%0,%1,%2,%3};"
        : "+f"(d[0]), "+f"(d[1]), "+f"(d[2]), "+f"(d[3])
        : "r"(a[0]), "r"(a[1]), "r"(a[2]), "r"(a[3]), "r"(b0), "r"(b1));
}

// ---------------- CSR construction ----------------
__global__ void k_init(int n) {
    int i = blockIdx.x * blockDim.x + threadIdx.x;
    if (i < n) g_ecnt[i] = 0;
    if (i < 3 * D) { g_sum[i] = 0.f; g_sq[i] = 0.f; }
}

__global__ void k_count(const int* __restrict__ ei, int E) {
    int e = blockIdx.x * blockDim.x + threadIdx.x;
    if (e < E) atomicAdd(&g_ecnt[ei[E + e]], 1);
}

__global__ void k_scan1(int n) {
    __shared__ int sm[1024];
    int tid = threadIdx.x;
    int i = blockIdx.x * 1024 + tid;
    int v = (i < n) ? g_ecnt[i] : 0;
    sm[tid] = v;
    __syncthreads();
    for (int off = 1; off < 1024; off <<= 1) {
        int t = (tid >= off) ? sm[tid - off] : 0;
        __syncthreads();
        sm[tid] += t;
        __syncthreads();
    }
    if (i < n) g_offs[i] = sm[tid] - v;
    if (tid == 1023) g_bsum[blockIdx.x] = sm[1023];
}

__global__ void k_scan2(int nb) {
    __shared__ int sm[128];
    int tid = threadIdx.x;
    int v = (tid < nb) ? g_bsum[tid] : 0;
    sm[tid] = v;
    __syncthreads();
    for (int off = 1; off < 128; off <<= 1) {
        int t = (tid >= off) ? sm[tid - off] : 0;
        __syncthreads();
        sm[tid] += t;
        __syncthreads();
    }
    g_bsumx[tid] = sm[tid] - v;
}

__global__ void k_scan3(int n) {
    int i = blockIdx.x * 1024 + threadIdx.x;
    if (i < n) {
        int o = g_offs[i] + g_bsumx[blockIdx.x];
        g_offs[i] = o;
        g_cur[i] = o;
        g_dinv[i] = rsqrtf((float)(g_ecnt[i] + 1));
    }
}

__global__ void k_bucket(const int* __restrict__ ei, int E) {
    int e = blockIdx.x * blockDim.x + threadIdx.x;
    if (e < E) {
        int dst = ei[E + e];
        int pos = atomicAdd(&g_cur[dst], 1);
        g_csr[pos] = ei[e];
    }
}

// ---------------- gather-sum + g + BN1 stats ----------------
__global__ void __launch_bounds__(256)
k_gather(const float* __restrict__ b, int n) {
    __shared__ float ss[8][128];
    __shared__ float sq[8][128];
    int tid = threadIdx.x;
    int warp = tid >> 5, lane = tid & 31;
    int c = lane * 4;
    int d = blockIdx.x * 8 + warp;

    float4 gv = make_float4(0.f, 0.f, 0.f, 0.f);
    if (d < n) {
        int st = g_offs[d];
        int ne = g_ecnt[d];
        float4 a0 = make_float4(0.f, 0.f, 0.f, 0.f);
        float4 a1 = make_float4(0.f, 0.f, 0.f, 0.f);
        int i = 0;
        for (; i + 2 <= ne; i += 2) {
            int sA = g_csr[st + i];
            int sB = g_csr[st + i + 1];
            float4 vA = *(const float4*)(g_hs + (size_t)sA * D + c);
            float4 vB = *(const float4*)(g_hs + (size_t)sB * D + c);
            a0.x += vA.x; a0.y += vA.y; a0.z += vA.z; a0.w += vA.w;
            a1.x += vB.x; a1.y += vB.y; a1.z += vB.z; a1.w += vB.w;
        }
        if (i < ne) {
            int sA = g_csr[st + i];
            float4 vA = *(const float4*)(g_hs + (size_t)sA * D + c);
            a0.x += vA.x; a0.y += vA.y; a0.z += vA.z; a0.w += vA.w;
        }
        float4 self = *(const float4*)(g_hs + (size_t)d * D + c);
        float dv = g_dinv[d];
        float4 bv = *(const float4*)(b + c);
        gv.x = dv * (a0.x + a1.x + self.x) + bv.x;
        gv.y = dv * (a0.y + a1.y + self.y) + bv.y;
        gv.z = dv * (a0.z + a1.z + self.z) + bv.z;
        gv.w = dv * (a0.w + a1.w + self.w) + bv.w;
        *(float4*)(g_acc + (size_t)d * D + c) = gv;
    }
    *(float4*)(&ss[warp][c]) = gv;
    *(float4*)(&sq[warp][c]) = make_float4(gv.x * gv.x, gv.y * gv.y, gv.z * gv.z, gv.w * gv.w);
    __syncthreads();
    if (tid < 128) {
        float s = 0.f, q = 0.f;
        #pragma unroll
        for (int w = 0; w < 8; w++) { s += ss[w][tid]; q += sq[w][tid]; }
        atomicAdd(&g_sum[tid], s);
        atomicAdd(&g_sq[tid], q);
    }
}

__global__ void k_finalize(const float* __restrict__ gamma, const float* __restrict__ beta,
                           int stage, float invn) {
    int i = threadIdx.x;
    if (i < D) {
        float m = g_sum[stage * D + i] * invn;
        float q = g_sq[stage * D + i] * invn;
        float var = q - m * m;
        float sc = gamma[i] * rsqrtf(var + 1e-5f);
        g_scale[stage * D + i] = sc;
        g_shift[stage * D + i] = beta[i] - m * sc;
    }
}

// r = x + relu(bn1(g)) -> stored into g_hs; accumulate BN2 stats
__global__ void k_r(const float* __restrict__ x, int n) {
    __shared__ float sm[512];
    int tid = threadIdx.x;
    int col = tid & (D - 1);
    int half = tid >> 7;
    int row0 = blockIdx.x * 256;
    float sc = g_scale[col];
    float sh = g_shift[col];
    float sum = 0.f, sq = 0.f;
    for (int rr = 0; rr < 128; rr++) {
        int row = row0 + rr * 2 + half;
        if (row < n) {
            size_t idx = (size_t)row * D + col;
            float g = g_acc[idx];
            float v = fmaxf(fmaf(g, sc, sh), 0.f);
            float r = x[idx] + v;
            g_hs[idx] = r;
            sum += r; sq += r * r;
        }
    }
    sm[tid] = sum; sm[256 + tid] = sq;
    __syncthreads();
    if (tid < 128) {
        float s = sm[tid] + sm[tid + 128];
        float q = sm[256 + tid] + sm[256 + tid + 128];
        atomicAdd(&g_sum[D + tid], s);
        atomicAdd(&g_sq[D + tid], q);
    }
}

__global__ void k_out(float* __restrict__ out, int n) {
    int i = blockIdx.x * blockDim.x + threadIdx.x;
    int total = n * 32;
    if (i < total) {
        int c4 = (i & 31) * 4;
        float4 v = *(const float4*)(g_acc + (size_t)i * 4);
        float4 s = *(const float4*)(g_scale + 2 * D + c4);
        float4 h = *(const float4*)(g_shift + 2 * D + c4);
        float4 o;
        o.x = fmaf(v.x, s.x, h.x);
        o.y = fmaf(v.y, s.y, h.y);
        o.z = fmaf(v.z, s.z, h.z);
        o.w = fmaf(v.w, s.w, h.w);
        *(float4*)(out + (size_t)i * 4) = o;
    }
}

// ---------------- bf16x3 mma.sync GEMM (R4 kernel, 8 warps) ----------------
// MODE 0: hs = (x @ W) * dinv[row]                   (A=x,  K=128, out cols 128)
// MODE 1: z  = relu((r*sc2+sh2) @ W1 + b1)           (A=hs, K=128, out cols 256 via grid.y)
// MODE 2: y  = z @ W2 + b2 + bn2(r); fused BN3 stats (A=z,  K=256, out cols 128)
template<int MODE, int KTOT>
__global__ void __launch_bounds__(256, 1)
k_mgemm(const float* __restrict__ Ain, const float* __restrict__ Wg,
        const float* __restrict__ bias, int M) {
    constexpr int LDW = (MODE == 1) ? 256 : 128;   // W row stride (floats)
    constexpr int LDO = (MODE == 1) ? 256 : 128;   // output row stride
    constexpr int AH = 0, AL = 16384, BH = 32768, BL = 49152;

    extern __shared__ char smem[];
    uint32_t sb = smem_u32(smem);
    __shared__ float s_s[128], s_q[128];

    int tid = threadIdx.x;
    int wid = tid >> 5;
    int lane = tid & 31;
    int warp_m = wid >> 1;          // 0..3 (32 rows each)
    int warp_n = wid & 1;           // 0..1 (64 cols each)
    int rowBase = blockIdx.x * 128;
    int colBase = blockIdx.y * 128; // only MODE 1 has grid.y = 2

    const float* A = (MODE == 0) ? Ain : (MODE == 1 ? g_hs : g_z);

    if (MODE == 2) {
        if (tid < 128) { s_s[tid] = 0.f; s_q[tid] = 0.f; }
    }

    float acc[2][8][4];
    #pragma unroll
    for (int mt = 0; mt < 2; mt++)
        #pragma unroll
        for (int j = 0; j < 8; j++)
            #pragma unroll
            for (int q = 0; q < 4; q++) acc[mt][j][q] = 0.f;

    for (int kt = 0; kt < KTOT / 64; kt++) {
        if (kt > 0) __syncthreads();
        // ---- stage A chunk [128 rows x 64 k] -> hi/lo bf16 planes ----
        #pragma unroll
        for (int it = 0; it < 4; it++) {
            int u = it * 256 + tid;          // 1024 16B units
            int r = u >> 3, c16 = u & 7;
            int gr = rowBase + r;
            int kk = kt * 64 + c16 * 8;
            float4 v0 = make_float4(0.f, 0.f, 0.f, 0.f), v1 = v0;
            if (gr < M) {
                const float* ap = A + (size_t)gr * KTOT + kk;
                v0 = *(const float4*)(ap);
                v1 = *(const float4*)(ap + 4);
            }
            if (MODE == 1) {
                float4 s0 = *(const float4*)(g_scale + D + kk);
                float4 s1 = *(const float4*)(g_scale + D + kk + 4);
                float4 h0 = *(const float4*)(g_shift + D + kk);
                float4 h1 = *(const float4*)(g_shift + D + kk + 4);
                v0.x = fmaf(v0.x, s0.x, h0.x); v0.y = fmaf(v0.y, s0.y, h0.y);
                v0.z = fmaf(v0.z, s0.z, h0.z); v0.w = fmaf(v0.w, s0.w, h0.w);
                v1.x = fmaf(v1.x, s1.x, h1.x); v1.y = fmaf(v1.y, s1.y, h1.y);
                v1.z = fmaf(v1.z, s1.z, h1.z); v1.w = fmaf(v1.w, s1.w, h1.w);
            }
            uint4 hiU, loU;
            split2(v0.x, v0.y, hiU.x, loU.x);
            split2(v0.z, v0.w, hiU.y, loU.y);
            split2(v1.x, v1.y, hiU.z, loU.z);
            split2(v1.z, v1.w, hiU.w, loU.w);
            int ofs = (r * 8 + (c16 ^ (r & 7))) * 16;
            *(uint4*)(smem + AH + ofs) = hiU;
            *(uint4*)(smem + AL + ofs) = loU;
        }
        // ---- stage B chunk: W[kt*64..+64][colBase..+128] -> hi/lo planes ----
        #pragma unroll
        for (int it = 0; it < 4; it++) {
            int u = it * 256 + tid;
            int k = u >> 4, c16 = u & 15;
            int gk = kt * 64 + k;
            const float* wp = Wg + (size_t)gk * LDW + colBase + c16 * 8;
            float4 v0 = *(const float4*)(wp);
            float4 v1 = *(const float4*)(wp + 4);
            uint4 hiU, loU;
            split2(v0.x, v0.y, hiU.x, loU.x);
            split2(v0.z, v0.w, hiU.y, loU.y);
            split2(v1.x, v1.y, hiU.z, loU.z);
            split2(v1.z, v1.w, hiU.w, loU.w);
            int ofs = (k * 16 + (c16 ^ (k & 7))) * 16;
            *(uint4*)(smem + BH + ofs) = hiU;
            *(uint4*)(smem + BL + ofs) = loU;
        }
        __syncthreads();
        // ---- compute 4 k16-steps ----
        #pragma unroll
        for (int ks = 0; ks < 4; ks++) {
            uint32_t ah[2][4], al[2][4];
            #pragma unroll
            for (int mt = 0; mt < 2; mt++) {
                int r = warp_m * 32 + mt * 16 + (lane & 15);
                int c16 = ks * 2 + (lane >> 4);
                uint32_t ad = sb + AH + (uint32_t)((r * 8 + (c16 ^ (r & 7))) * 16);
                ldsm_x4(ah[mt], ad);
                ldsm_x4(al[mt], ad + 16384);
            }
            uint32_t bh[4][4], bl[4][4];
            #pragma unroll
            for (int g = 0; g < 4; g++) {
                int k = ks * 16 + (lane & 15);
                int c16 = warp_n * 8 + g * 2 + (lane >> 4);
                uint32_t bd = sb + BH + (uint32_t)((k * 16 + (c16 ^ (k & 7))) * 16);
                ldsm_x4_t(bh[g], bd);
                ldsm_x4_t(bl[g], bd + 16384);
            }
            #pragma unroll
            for (int mt = 0; mt < 2; mt++)
                #pragma unroll
                for (int j = 0; j < 8; j++) {
                    int g = j >> 1, s = (j & 1) * 2;
                    mma16816(acc[mt][j], ah[mt], bh[g][s], bh[g][s + 1]);
                    mma16816(acc[mt][j], ah[mt], bl[g][s], bl[g][s + 1]);
                    mma16816(acc[mt][j], al[mt], bh[g][s], bh[g][s + 1]);
                }
        }
    }

    // ---- epilogue ----
    int lane4 = lane >> 2;
    int lane2 = (lane & 3) * 2;
    #pragma unroll
    for (int mt = 0; mt < 2; mt++) {
        int r0 = rowBase + warp_m * 32 + mt * 16 + lane4;   // and r0+8
        #pragma unroll
        for (int j = 0; j < 8; j++) {
            int gc = colBase + warp_n * 64 + j * 8 + lane2;
            float c0 = acc[mt][j][0], c1 = acc[mt][j][1];
            float c2 = acc[mt][j][2], c3 = acc[mt][j][3];
            if (MODE == 0) {
                if (r0 < M) {
                    float dv = g_dinv[r0];
                    *(float2*)(g_hs + (size_t)r0 * LDO + gc) = make_float2(c0 * dv, c1 * dv);
                }
                if (r0 + 8 < M) {
                    float dv = g_dinv[r0 + 8];
                    *(float2*)(g_hs + (size_t)(r0 + 8) * LDO + gc) = make_float2(c2 * dv, c3 * dv);
                }
            } else if (MODE == 1) {
                float2 bv = *(const float2*)(bias + gc);
                if (r0 < M)
                    *(float2*)(g_z + (size_t)r0 * LDO + gc) =
                        make_float2(fmaxf(c0 + bv.x, 0.f), fmaxf(c1 + bv.y, 0.f));
                if (r0 + 8 < M)
                    *(float2*)(g_z + (size_t)(r0 + 8) * LDO + gc) =
                        make_float2(fmaxf(c2 + bv.x, 0.f), fmaxf(c3 + bv.y, 0.f));
            } else {
                float2 bv = *(const float2*)(bias + gc);
                float2 sc = *(const float2*)(g_scale + D + gc);
                float2 sh = *(const float2*)(g_shift + D + gc);
                float as0 = 0.f, as1 = 0.f, aq0 = 0.f, aq1 = 0.f;
                if (r0 < M) {
                    float2 rv = *(const float2*)(g_hs + (size_t)r0 * 128 + gc);
                    float y0 = c0 + bv.x + fmaf(rv.x, sc.x, sh.x);
                    float y1 = c1 + bv.y + fmaf(rv.y, sc.y, sh.y);
                    *(float2*)(g_acc + (size_t)r0 * LDO + gc) = make_float2(y0, y1);
                    as0 += y0; as1 += y1; aq0 += y0 * y0; aq1 += y1 * y1;
                }
                if (r0 + 8 < M) {
                    float2 rv = *(const float2*)(g_hs + (size_t)(r0 + 8) * 128 + gc);
                    float y2 = c2 + bv.x + fmaf(rv.x, sc.x, sh.x);
                    float y3 = c3 + bv.y + fmaf(rv.y, sc.y, sh.y);
                    *(float2*)(g_acc + (size_t)(r0 + 8) * LDO + gc) = make_float2(y2, y3);
                    as0 += y2; as1 += y3; aq0 += y2 * y2; aq1 += y3 * y3;
                }
                atomicAdd(&s_s[gc], as0);
                atomicAdd(&s_s[gc + 1], as1);
                atomicAdd(&s_q[gc], aq0);
                atomicAdd(&s_q[gc + 1], aq1);
            }
        }
    }
    if (MODE == 2) {
        __syncthreads();
        if (tid < 128) {
            atomicAdd(&g_sum[2 * D + tid], s_s[tid]);
            atomicAdd(&g_sq[2 * D + tid], s_q[tid]);
        }
    }
}

// ---------------- launch ----------------
extern "C" void kernel_launch(void* const* d_in, const int* in_sizes, int n_in,
                              void* d_out, int out_size) {
    const float* x      = (const float*)d_in[0];
    const int*   ei     = (const int*)  d_in[1];
    const float* W      = (const float*)d_in[2];
    const float* b      = (const float*)d_in[3];
    const float* gamma1 = (const float*)d_in[4];
    const float* beta1  = (const float*)d_in[5];
    const float* gamma2 = (const float*)d_in[6];
    const float* beta2  = (const float*)d_in[7];
    const float* gamma3 = (const float*)d_in[8];
    const float* beta3  = (const float*)d_in[9];
    const float* W1     = (const float*)d_in[10];
    const float* b1     = (const float*)d_in[11];
    const float* W2     = (const float*)d_in[12];
    const float* b2     = (const float*)d_in[13];
    float* out = (float*)d_out;

    int N = in_sizes[0] / D;
    int E = in_sizes[1] / 2;
    float invn = 1.0f / (float)N;

    int smemB = 65536;
    cudaFuncSetAttribute(k_mgemm<0, 128>, cudaFuncAttributeMaxDynamicSharedMemorySize, smemB);
    cudaFuncSetAttribute(k_mgemm<1, 128>, cudaFuncAttributeMaxDynamicSharedMemorySize, smemB);
    cudaFuncSetAttribute(k_mgemm<2, 256>, cudaFuncAttributeMaxDynamicSharedMemorySize, smemB);

    int nb = (N + 255) / 256;
    int gb = (N + 127) / 128;
    int sblocks = (N + 1023) / 1024;

    k_init<<<nb, 256>>>(N);
    k_count<<<(E + 255) / 256, 256>>>(ei, E);
    k_scan1<<<sblocks, 1024>>>(N);
    k_scan2<<<1, 128>>>(sblocks);
    k_scan3<<<sblocks, 1024>>>(N);
    k_bucket<<<(E + 255) / 256, 256>>>(ei, E);
    k_mgemm<0, 128><<<gb, 256, smemB>>>(x, W, (const float*)0, N);
    k_gather<<<(N + 7) / 8, 256>>>(b, N);
    k_finalize<<<1, 128>>>(gamma1, beta1, 0, invn);
    k_r<<<(N + 255) / 256, 256>>>(x, N);
    k_finalize<<<1, 128>>>(gamma2, beta2, 1, invn);
    k_mgemm<1, 128><<<dim3(gb, 2), 256, smemB>>>((const float*)0, W1, b1, N);
    k_mgemm<2, 256><<<gb, 256, smemB>>>((const float*)0, W2, b2, N);
    k_finalize<<<1, 128>>>(gamma3, beta3, 2, invn);
    k_out<<<(N * 32 + 255) / 256, 256>>>(out, N);
}

// round 16
// speedup vs baseline: 1.2474x; 1.2474x over previous
#include <cuda_runtime.h>
#include <cuda_bf16.h>
#include <stdint.h>

#define D 128
#define D2 256
#define NMAX 100096
#define EMAX 3205120

// ---------------- scratch (device globals; no allocation) ----------------
__device__ __align__(16) float g_hs [(size_t)NMAX * D];   // h_scaled, later r
__device__ __align__(16) float g_acc[(size_t)NMAX * D];   // g, later y
__device__ __align__(16) float g_z  [(size_t)NMAX * D2];  // FFN hidden
__device__ int   g_ecnt[NMAX];
__device__ int   g_offs[NMAX];
__device__ int   g_cur [NMAX];
__device__ int   g_csr [EMAX];
__device__ int   g_bsum [128];
__device__ int   g_bsumx[128];
__device__ float g_dinv[NMAX];
__device__ float g_sum [3 * D];
__device__ float g_sq  [3 * D];
__device__ float g_scale[3 * D];
__device__ float g_shift[3 * D];

// ---------------- helpers ----------------
__device__ __forceinline__ uint32_t smem_u32(const void* p) {
    uint32_t a;
    asm("{ .reg .u64 t; cvta.to.shared.u64 t, %1; cvt.u32.u64 %0, t; }" : "=r"(a) : "l"(p));
    return a;
}
__device__ __forceinline__ void split2(float a, float b, uint32_t& hi, uint32_t& lo) {
    __nv_bfloat16 ha = __float2bfloat16(a), hb = __float2bfloat16(b);
    float ra = a - __bfloat162float(ha);
    float rb = b - __bfloat162float(hb);
    __nv_bfloat16 la = __float2bfloat16(ra), lb = __float2bfloat16(rb);
    hi = (uint32_t)__bfloat16_as_ushort(ha) | ((uint32_t)__bfloat16_as_ushort(hb) << 16);
    lo = (uint32_t)__bfloat16_as_ushort(la) | ((uint32_t)__bfloat16_as_ushort(lb) << 16);
}
__device__ __forceinline__ void ldsm_x4(uint32_t* r, uint32_t addr) {
    asm volatile("ldmatrix.sync.aligned.m8n8.x4.shared.b16 {%0,%1,%2,%3}, [%4];"
                 : "=r"(r[0]), "=r"(r[1]), "=r"(r[2]), "=r"(r[3]) : "r"(addr));
}
__device__ __forceinline__ void ldsm_x4_t(uint32_t* r, uint32_t addr) {
    asm volatile("ldmatrix.sync.aligned.m8n8.x4.trans.shared.b16 {%0,%1,%2,%3}, [%4];"
                 : "=r"(r[0]), "=r"(r[1]), "=r"(r[2]), "=r"(r[3]) : "r"(addr));
}
__device__ __forceinline__ void mma16816(float* d, const uint32_t* a, uint32_t b0, uint32_t b1) {
    asm volatile(
        "mma.sync.aligned.m16n8k16.row.col.f32.bf16.bf16.f32 "
        "{%0,%1,%2,%3}, {%4,%5,%6,%7}, {%8,%9}, {%0,%1,%2,%3};"
        : "+f"(d[0]), "+f"(d[1]), "+f"(d[2]), "+f"(d[3])
        : "r"(a[0]), "r"(a[1]), "r"(a[2]), "r"(a[3]), "r"(b0), "r"(b1));
}

// ---------------- CSR construction ----------------
__global__ void k_count(const int* __restrict__ ei, int E) {
    int e = blockIdx.x * blockDim.x + threadIdx.x;
    if (e < E) atomicAdd(&g_ecnt[ei[E + e]], 1);
}

__global__ void k_scan1(int n) {
    __shared__ int sm[1024];
    int tid = threadIdx.x;
    int i = blockIdx.x * 1024 + tid;
    int v = (i < n) ? g_ecnt[i] : 0;
    sm[tid] = v;
    __syncthreads();
    for (int off = 1; off < 1024; off <<= 1) {
        int t = (tid >= off) ? sm[tid - off] : 0;
        __syncthreads();
        sm[tid] += t;
        __syncthreads();
    }
    if (i < n) g_offs[i] = sm[tid] - v;
    if (tid == 1023) g_bsum[blockIdx.x] = sm[1023];
}

__global__ void k_scan2(int nb) {
    __shared__ int sm[128];
    int tid = threadIdx.x;
    int v = (tid < nb) ? g_bsum[tid] : 0;
    sm[tid] = v;
    __syncthreads();
    for (int off = 1; off < 128; off <<= 1) {
        int t = (tid >= off) ? sm[tid - off] : 0;
        __syncthreads();
        sm[tid] += t;
        __syncthreads();
    }
    g_bsumx[tid] = sm[tid] - v;
}

__global__ void k_scan3(int n) {
    int i = blockIdx.x * 1024 + threadIdx.x;
    if (i < n) {
        int o = g_offs[i] + g_bsumx[blockIdx.x];
        g_offs[i] = o;
        g_cur[i] = o;
        g_dinv[i] = rsqrtf((float)(g_ecnt[i] + 1));
    }
}

__global__ void k_bucket(const int* __restrict__ ei, int E) {
    int e = blockIdx.x * blockDim.x + threadIdx.x;
    if (e < E) {
        int dst = ei[E + e];
        int pos = atomicAdd(&g_cur[dst], 1);
        g_csr[pos] = ei[e];
    }
}

// ---------------- gather-sum + g + BN1 stats ----------------
// one warp per dst; lane handles 4 columns; 4-way unrolled accumulators (MLP=4)
__global__ void __launch_bounds__(256)
k_gather(const float* __restrict__ b, int n) {
    __shared__ float ss[8][128];
    __shared__ float sq[8][128];
    int tid = threadIdx.x;
    int warp = tid >> 5, lane = tid & 31;
    int c = lane * 4;
    int d = blockIdx.x * 8 + warp;

    float4 gv = make_float4(0.f, 0.f, 0.f, 0.f);
    if (d < n) {
        int st = g_offs[d];
        int ne = g_ecnt[d];
        float4 a0 = make_float4(0.f, 0.f, 0.f, 0.f);
        float4 a1 = make_float4(0.f, 0.f, 0.f, 0.f);
        float4 a2 = make_float4(0.f, 0.f, 0.f, 0.f);
        float4 a3 = make_float4(0.f, 0.f, 0.f, 0.f);
        int i = 0;
        for (; i + 4 <= ne; i += 4) {
            int sA = g_csr[st + i];
            int sB = g_csr[st + i + 1];
            int sC = g_csr[st + i + 2];
            int sD = g_csr[st + i + 3];
            float4 vA = *(const float4*)(g_hs + (size_t)sA * D + c);
            float4 vB = *(const float4*)(g_hs + (size_t)sB * D + c);
            float4 vC = *(const float4*)(g_hs + (size_t)sC * D + c);
            float4 vD = *(const float4*)(g_hs + (size_t)sD * D + c);
            a0.x += vA.x; a0.y += vA.y; a0.z += vA.z; a0.w += vA.w;
            a1.x += vB.x; a1.y += vB.y; a1.z += vB.z; a1.w += vB.w;
            a2.x += vC.x; a2.y += vC.y; a2.z += vC.z; a2.w += vC.w;
            a3.x += vD.x; a3.y += vD.y; a3.z += vD.z; a3.w += vD.w;
        }
        for (; i < ne; i++) {
            int sA = g_csr[st + i];
            float4 vA = *(const float4*)(g_hs + (size_t)sA * D + c);
            a0.x += vA.x; a0.y += vA.y; a0.z += vA.z; a0.w += vA.w;
        }
        float4 self = *(const float4*)(g_hs + (size_t)d * D + c);
        float dv = g_dinv[d];
        float4 bv = *(const float4*)(b + c);
        gv.x = dv * ((a0.x + a1.x) + (a2.x + a3.x) + self.x) + bv.x;
        gv.y = dv * ((a0.y + a1.y) + (a2.y + a3.y) + self.y) + bv.y;
        gv.z = dv * ((a0.z + a1.z) + (a2.z + a3.z) + self.z) + bv.z;
        gv.w = dv * ((a0.w + a1.w) + (a2.w + a3.w) + self.w) + bv.w;
        *(float4*)(g_acc + (size_t)d * D + c) = gv;
    }
    *(float4*)(&ss[warp][c]) = gv;
    *(float4*)(&sq[warp][c]) = make_float4(gv.x * gv.x, gv.y * gv.y, gv.z * gv.z, gv.w * gv.w);
    __syncthreads();
    if (tid < 128) {
        float s = 0.f, q = 0.f;
        #pragma unroll
        for (int w = 0; w < 8; w++) { s += ss[w][tid]; q += sq[w][tid]; }
        atomicAdd(&g_sum[tid], s);
        atomicAdd(&g_sq[tid], q);
    }
}

__global__ void k_finalize(const float* __restrict__ gamma, const float* __restrict__ beta,
                           int stage, float invn) {
    int i = threadIdx.x;
    if (i < D) {
        float m = g_sum[stage * D + i] * invn;
        float q = g_sq[stage * D + i] * invn;
        float var = q - m * m;
        float sc = gamma[i] * rsqrtf(var + 1e-5f);
        g_scale[stage * D + i] = sc;
        g_shift[stage * D + i] = beta[i] - m * sc;
    }
}

// r = x + relu(bn1(g)) -> stored into g_hs; accumulate BN2 stats
__global__ void k_r(const float* __restrict__ x, int n) {
    __shared__ float sm[512];
    int tid = threadIdx.x;
    int col = tid & (D - 1);
    int half = tid >> 7;
    int row0 = blockIdx.x * 256;
    float sc = g_scale[col];
    float sh = g_shift[col];
    float sum = 0.f, sq = 0.f;
    for (int rr = 0; rr < 128; rr++) {
        int row = row0 + rr * 2 + half;
        if (row < n) {
            size_t idx = (size_t)row * D + col;
            float g = g_acc[idx];
            float v = fmaxf(fmaf(g, sc, sh), 0.f);
            float r = x[idx] + v;
            g_hs[idx] = r;
            sum += r; sq += r * r;
        }
    }
    sm[tid] = sum; sm[256 + tid] = sq;
    __syncthreads();
    if (tid < 128) {
        float s = sm[tid] + sm[tid + 128];
        float q = sm[256 + tid] + sm[256 + tid + 128];
        atomicAdd(&g_sum[D + tid], s);
        atomicAdd(&g_sq[D + tid], q);
    }
}

// BN3 stats over y (= g_acc)
__global__ void k_ystats(int n) {
    __shared__ float sm[512];
    int tid = threadIdx.x;
    int col = tid & (D - 1);
    int half = tid >> 7;
    int row0 = blockIdx.x * 256;
    float sum = 0.f, sq = 0.f;
    for (int rr = 0; rr < 128; rr++) {
        int row = row0 + rr * 2 + half;
        if (row < n) {
            float y = g_acc[(size_t)row * D + col];
            sum += y; sq += y * y;
        }
    }
    sm[tid] = sum; sm[256 + tid] = sq;
    __syncthreads();
    if (tid < 128) {
        float s = sm[tid] + sm[tid + 128];
        float q = sm[256 + tid] + sm[256 + tid + 128];
        atomicAdd(&g_sum[2 * D + tid], s);
        atomicAdd(&g_sq[2 * D + tid], q);
    }
}

__global__ void k_out(float* __restrict__ out, int n) {
    int i = blockIdx.x * blockDim.x + threadIdx.x;
    int total = n * 32;
    if (i < total) {
        int c4 = (i & 31) * 4;
        float4 v = *(const float4*)(g_acc + (size_t)i * 4);
        float4 s = *(const float4*)(g_scale + 2 * D + c4);
        float4 h = *(const float4*)(g_shift + 2 * D + c4);
        float4 o;
        o.x = fmaf(v.x, s.x, h.x);
        o.y = fmaf(v.y, s.y, h.y);
        o.z = fmaf(v.z, s.z, h.z);
        o.w = fmaf(v.w, s.w, h.w);
        *(float4*)(out + (size_t)i * 4) = o;
    }
}

// ---------------- bf16x3 mma.sync GEMM (R4 kernel, 8 warps) ----------------
// MODE 0: hs = (x @ W) * dinv[row]                   (A=x,  K=128, out cols 128)
// MODE 1: z  = relu((r*sc2+sh2) @ W1 + b1)           (A=hs, K=128, out cols 256 via grid.y)
// MODE 2: y  = z @ W2 + b2 + bn2(r)                  (A=z,  K=256, out cols 128)
template<int MODE, int KTOT>
__global__ void __launch_bounds__(256, 1)
k_mgemm(const float* __restrict__ Ain, const float* __restrict__ Wg,
        const float* __restrict__ bias, int M) {
    constexpr int LDW = (MODE == 1) ? 256 : 128;   // W row stride (floats)
    constexpr int LDO = (MODE == 1) ? 256 : 128;   // output row stride
    constexpr int AH = 0, AL = 16384, BH = 32768, BL = 49152;

    extern __shared__ char smem[];
    uint32_t sb = smem_u32(smem);
    int tid = threadIdx.x;
    int wid = tid >> 5;
    int lane = tid & 31;
    int warp_m = wid >> 1;          // 0..3 (32 rows each)
    int warp_n = wid & 1;           // 0..1 (64 cols each)
    int rowBase = blockIdx.x * 128;
    int colBase = blockIdx.y * 128; // only MODE 1 has grid.y = 2

    const float* A = (MODE == 0) ? Ain : (MODE == 1 ? g_hs : g_z);

    float acc[2][8][4];
    #pragma unroll
    for (int mt = 0; mt < 2; mt++)
        #pragma unroll
        for (int j = 0; j < 8; j++)
            #pragma unroll
            for (int q = 0; q < 4; q++) acc[mt][j][q] = 0.f;

    for (int kt = 0; kt < KTOT / 64; kt++) {
        if (kt > 0) __syncthreads();
        // ---- stage A chunk [128 rows x 64 k] -> hi/lo bf16 planes ----
        #pragma unroll
        for (int it = 0; it < 4; it++) {
            int u = it * 256 + tid;          // 1024 16B units
            int r = u >> 3, c16 = u & 7;
            int gr = rowBase + r;
            int kk = kt * 64 + c16 * 8;
            float4 v0 = make_float4(0.f, 0.f, 0.f, 0.f), v1 = v0;
            if (gr < M) {
                const float* ap = A + (size_t)gr * KTOT + kk;
                v0 = *(const float4*)(ap);
                v1 = *(const float4*)(ap + 4);
            }
            if (MODE == 1) {
                float4 s0 = *(const float4*)(g_scale + D + kk);
                float4 s1 = *(const float4*)(g_scale + D + kk + 4);
                float4 h0 = *(const float4*)(g_shift + D + kk);
                float4 h1 = *(const float4*)(g_shift + D + kk + 4);
                v0.x = fmaf(v0.x, s0.x, h0.x); v0.y = fmaf(v0.y, s0.y, h0.y);
                v0.z = fmaf(v0.z, s0.z, h0.z); v0.w = fmaf(v0.w, s0.w, h0.w);
                v1.x = fmaf(v1.x, s1.x, h1.x); v1.y = fmaf(v1.y, s1.y, h1.y);
                v1.z = fmaf(v1.z, s1.z, h1.z); v1.w = fmaf(v1.w, s1.w, h1.w);
            }
            uint4 hiU, loU;
            split2(v0.x, v0.y, hiU.x, loU.x);
            split2(v0.z, v0.w, hiU.y, loU.y);
            split2(v1.x, v1.y, hiU.z, loU.z);
            split2(v1.z, v1.w, hiU.w, loU.w);
            int ofs = (r * 8 + (c16 ^ (r & 7))) * 16;
            *(uint4*)(smem + AH + ofs) = hiU;
            *(uint4*)(smem + AL + ofs) = loU;
        }
        // ---- stage B chunk: W[kt*64..+64][colBase..+128] -> hi/lo planes ----
        #pragma unroll
        for (int it = 0; it < 4; it++) {
            int u = it * 256 + tid;
            int k = u >> 4, c16 = u & 15;
            int gk = kt * 64 + k;
            const float* wp = Wg + (size_t)gk * LDW + colBase + c16 * 8;
            float4 v0 = *(const float4*)(wp);
            float4 v1 = *(const float4*)(wp + 4);
            uint4 hiU, loU;
            split2(v0.x, v0.y, hiU.x, loU.x);
            split2(v0.z, v0.w, hiU.y, loU.y);
            split2(v1.x, v1.y, hiU.z, loU.z);
            split2(v1.z, v1.w, hiU.w, loU.w);
            int ofs = (k * 16 + (c16 ^ (k & 7))) * 16;
            *(uint4*)(smem + BH + ofs) = hiU;
            *(uint4*)(smem + BL + ofs) = loU;
        }
        __syncthreads();
        // ---- compute 4 k16-steps ----
        #pragma unroll
        for (int ks = 0; ks < 4; ks++) {
            uint32_t ah[2][4], al[2][4];
            #pragma unroll
            for (int mt = 0; mt < 2; mt++) {
                int r = warp_m * 32 + mt * 16 + (lane & 15);
                int c16 = ks * 2 + (lane >> 4);
                uint32_t ad = sb + AH + (uint32_t)((r * 8 + (c16 ^ (r & 7))) * 16);
                ldsm_x4(ah[mt], ad);
                ldsm_x4(al[mt], ad + 16384);
            }
            uint32_t bh[4][4], bl[4][4];
            #pragma unroll
            for (int g = 0; g < 4; g++) {
                int k = ks * 16 + (lane & 15);
                int c16 = warp_n * 8 + g * 2 + (lane >> 4);
                uint32_t bd = sb + BH + (uint32_t)((k * 16 + (c16 ^ (k & 7))) * 16);
                ldsm_x4_t(bh[g], bd);
                ldsm_x4_t(bl[g], bd + 16384);
            }
            #pragma unroll
            for (int mt = 0; mt < 2; mt++)
                #pragma unroll
                for (int j = 0; j < 8; j++) {
                    int g = j >> 1, s = (j & 1) * 2;
                    mma16816(acc[mt][j], ah[mt], bh[g][s], bh[g][s + 1]);
                    mma16816(acc[mt][j], ah[mt], bl[g][s], bl[g][s + 1]);
                    mma16816(acc[mt][j], al[mt], bh[g][s], bh[g][s + 1]);
                }
        }
    }

    // ---- epilogue ----
    int lane4 = lane >> 2;
    int lane2 = (lane & 3) * 2;
    #pragma unroll
    for (int mt = 0; mt < 2; mt++) {
        int r0 = rowBase + warp_m * 32 + mt * 16 + lane4;   // and r0+8
        #pragma unroll
        for (int j = 0; j < 8; j++) {
            int gc = colBase + warp_n * 64 + j * 8 + lane2;
            float c0 = acc[mt][j][0], c1 = acc[mt][j][1];
            float c2 = acc[mt][j][2], c3 = acc[mt][j][3];
            if (MODE == 0) {
                if (r0 < M) {
                    float dv = g_dinv[r0];
                    *(float2*)(g_hs + (size_t)r0 * LDO + gc) = make_float2(c0 * dv, c1 * dv);
                }
                if (r0 + 8 < M) {
                    float dv = g_dinv[r0 + 8];
                    *(float2*)(g_hs + (size_t)(r0 + 8) * LDO + gc) = make_float2(c2 * dv, c3 * dv);
                }
            } else if (MODE == 1) {
                float2 bv = *(const float2*)(bias + gc);
                if (r0 < M)
                    *(float2*)(g_z + (size_t)r0 * LDO + gc) =
                        make_float2(fmaxf(c0 + bv.x, 0.f), fmaxf(c1 + bv.y, 0.f));
                if (r0 + 8 < M)
                    *(float2*)(g_z + (size_t)(r0 + 8) * LDO + gc) =
                        make_float2(fmaxf(c2 + bv.x, 0.f), fmaxf(c3 + bv.y, 0.f));
            } else {
                float2 bv = *(const float2*)(bias + gc);
                float2 sc = *(const float2*)(g_scale + D + gc);
                float2 sh = *(const float2*)(g_shift + D + gc);
                if (r0 < M) {
                    float2 rv = *(const float2*)(g_hs + (size_t)r0 * 128 + gc);
                    float y0 = c0 + bv.x + fmaf(rv.x, sc.x, sh.x);
                    float y1 = c1 + bv.y + fmaf(rv.y, sc.y, sh.y);
                    *(float2*)(g_acc + (size_t)r0 * LDO + gc) = make_float2(y0, y1);
                }
                if (r0 + 8 < M) {
                    float2 rv = *(const float2*)(g_hs + (size_t)(r0 + 8) * 128 + gc);
                    float y2 = c2 + bv.x + fmaf(rv.x, sc.x, sh.x);
                    float y3 = c3 + bv.y + fmaf(rv.y, sc.y, sh.y);
                    *(float2*)(g_acc + (size_t)(r0 + 8) * LDO + gc) = make_float2(y2, y3);
                }
            }
        }
    }
}

// ---------------- launch ----------------
extern "C" void kernel_launch(void* const* d_in, const int* in_sizes, int n_in,
                              void* d_out, int out_size) {
    const float* x      = (const float*)d_in[0];
    const int*   ei     = (const int*)  d_in[1];
    const float* W      = (const float*)d_in[2];
    const float* b      = (const float*)d_in[3];
    const float* gamma1 = (const float*)d_in[4];
    const float* beta1  = (const float*)d_in[5];
    const float* gamma2 = (const float*)d_in[6];
    const float* beta2  = (const float*)d_in[7];
    const float* gamma3 = (const float*)d_in[8];
    const float* beta3  = (const float*)d_in[9];
    const float* W1     = (const float*)d_in[10];
    const float* b1     = (const float*)d_in[11];
    const float* W2     = (const float*)d_in[12];
    const float* b2     = (const float*)d_in[13];
    float* out = (float*)d_out;

    int N = in_sizes[0] / D;
    int E = in_sizes[1] / 2;
    float invn = 1.0f / (float)N;

    int smemB = 65536;
    cudaFuncSetAttribute(k_mgemm<0, 128>, cudaFuncAttributeMaxDynamicSharedMemorySize, smemB);
    cudaFuncSetAttribute(k_mgemm<1, 128>, cudaFuncAttributeMaxDynamicSharedMemorySize, smemB);
    cudaFuncSetAttribute(k_mgemm<2, 256>, cudaFuncAttributeMaxDynamicSharedMemorySize, smemB);

    void *p_ecnt, *p_sum, *p_sq;
    cudaGetSymbolAddress(&p_ecnt, g_ecnt);
    cudaGetSymbolAddress(&p_sum, g_sum);
    cudaGetSymbolAddress(&p_sq, g_sq);

    int gb = (N + 127) / 128;
    int sblocks = (N + 1023) / 1024;

    cudaMemsetAsync(p_ecnt, 0, (size_t)N * sizeof(int), 0);
    cudaMemsetAsync(p_sum, 0, 3 * D * sizeof(float), 0);
    cudaMemsetAsync(p_sq, 0, 3 * D * sizeof(float), 0);
    k_count<<<(E + 255) / 256, 256>>>(ei, E);
    k_scan1<<<sblocks, 1024>>>(N);
    k_scan2<<<1, 128>>>(sblocks);
    k_scan3<<<sblocks, 1024>>>(N);
    k_bucket<<<(E + 255) / 256, 256>>>(ei, E);
    k_mgemm<0, 128><<<gb, 256, smemB>>>(x, W, (const float*)0, N);
    k_gather<<<(N + 7) / 8, 256>>>(b, N);
    k_finalize<<<1, 128>>>(gamma1, beta1, 0, invn);
    k_r<<<(N + 255) / 256, 256>>>(x, N);
    k_finalize<<<1, 128>>>(gamma2, beta2, 1, invn);
    k_mgemm<1, 128><<<dim3(gb, 2), 256, smemB>>>((const float*)0, W1, b1, N);
    k_mgemm<2, 256><<<gb, 256, smemB>>>((const float*)0, W2, b2, N);
    k_ystats<<<(N + 255) / 256, 256>>>(N);
    k_finalize<<<1, 128>>>(gamma3, beta3, 2, invn);
    k_out<<<(N * 32 + 255) / 256, 256>>>(out, N);
}

// round 17
// speedup vs baseline: 1.4882x; 1.1930x over previous
#include <cuda_runtime.h>
#include <cuda_bf16.h>
#include <stdint.h>

#define D 128
#define D2 256
#define NMAX 100096
#define EMAX 3205120

// ---------------- scratch (device globals; no allocation) ----------------
__device__ __align__(16) float g_hs [(size_t)NMAX * D];   // h_scaled, later r
__device__ __align__(16) float g_acc[(size_t)NMAX * D];   // g, later y
__device__ __align__(16) float g_z  [(size_t)NMAX * D2];  // FFN hidden
__device__ int   g_ecnt[NMAX];
__device__ int   g_offs[NMAX];
__device__ int   g_cur [NMAX];
__device__ int   g_csr [EMAX];
__device__ int   g_bsum [128];
__device__ int   g_bsumx[128];
__device__ float g_dinv[NMAX];
__device__ float g_sum [3 * D];
__device__ float g_sq  [3 * D];
__device__ float g_scale[3 * D];
__device__ float g_shift[3 * D];

// ---------------- helpers ----------------
__device__ __forceinline__ uint32_t smem_u32(const void* p) {
    uint32_t a;
    asm("{ .reg .u64 t; cvta.to.shared.u64 t, %1; cvt.u32.u64 %0, t; }" : "=r"(a) : "l"(p));
    return a;
}
__device__ __forceinline__ void split2(float a, float b, uint32_t& hi, uint32_t& lo) {
    __nv_bfloat16 ha = __float2bfloat16(a), hb = __float2bfloat16(b);
    float ra = a - __bfloat162float(ha);
    float rb = b - __bfloat162float(hb);
    __nv_bfloat16 la = __float2bfloat16(ra), lb = __float2bfloat16(rb);
    hi = (uint32_t)__bfloat16_as_ushort(ha) | ((uint32_t)__bfloat16_as_ushort(hb) << 16);
    lo = (uint32_t)__bfloat16_as_ushort(la) | ((uint32_t)__bfloat16_as_ushort(lb) << 16);
}
__device__ __forceinline__ void ldsm_x4(uint32_t* r, uint32_t addr) {
    asm volatile("ldmatrix.sync.aligned.m8n8.x4.shared.b16 {%0,%1,%2,%3}, [%4];"
                 : "=r"(r[0]), "=r"(r[1]), "=r"(r[2]), "=r"(r[3]) : "r"(addr));
}
__device__ __forceinline__ void ldsm_x4_t(uint32_t* r, uint32_t addr) {
    asm volatile("ldmatrix.sync.aligned.m8n8.x4.trans.shared.b16 {%0,%1,%2,%3}, [%4];"
                 : "=r"(r[0]), "=r"(r[1]), "=r"(r[2]), "=r"(r[3]) : "r"(addr));
}
__device__ __forceinline__ void mma16816(float* d, const uint32_t* a, uint32_t b0, uint32_t b1) {
    asm volatile(
        "mma.sync.aligned.m16n8k16.row.col.f32.bf16.bf16.f32 "
        "{%0,%1,%2,%3}, {%4,%5,%6,%7}, {%8,%9}, {%0,%1,%2,%3};"
        : "+f"(d[0]), "+f"(d[1]), "+f"(d[2]), "+f"(d[3])
        : "r"(a[0]), "r"(a[1]), "r"(a[2]), "r"(a[3]), "r"(b0), "r"(b1));
}

// ---------------- CSR construction ----------------
__global__ void k_count(const int* __restrict__ ei, int E) {
    int e = blockIdx.x * blockDim.x + threadIdx.x;
    if (e < E) atomicAdd(&g_ecnt[ei[E + e]], 1);
}

__global__ void k_scan1(int n) {
    __shared__ int sm[1024];
    int tid = threadIdx.x;
    int i = blockIdx.x * 1024 + tid;
    int v = (i < n) ? g_ecnt[i] : 0;
    sm[tid] = v;
    __syncthreads();
    for (int off = 1; off < 1024; off <<= 1) {
        int t = (tid >= off) ? sm[tid - off] : 0;
        __syncthreads();
        sm[tid] += t;
        __syncthreads();
    }
    if (i < n) g_offs[i] = sm[tid] - v;
    if (tid == 1023) g_bsum[blockIdx.x] = sm[1023];
}

__global__ void k_scan2(int nb) {
    __shared__ int sm[128];
    int tid = threadIdx.x;
    int v = (tid < nb) ? g_bsum[tid] : 0;
    sm[tid] = v;
    __syncthreads();
    for (int off = 1; off < 128; off <<= 1) {
        int t = (tid >= off) ? sm[tid - off] : 0;
        __syncthreads();
        sm[tid] += t;
        __syncthreads();
    }
    g_bsumx[tid] = sm[tid] - v;
}

__global__ void k_scan3(int n) {
    int i = blockIdx.x * 1024 + threadIdx.x;
    if (i < n) {
        int o = g_offs[i] + g_bsumx[blockIdx.x];
        g_offs[i] = o;
        g_cur[i] = o;
        g_dinv[i] = rsqrtf((float)(g_ecnt[i] + 1));
    }
}

__global__ void k_bucket(const int* __restrict__ ei, int E) {
    int e = blockIdx.x * blockDim.x + threadIdx.x;
    if (e < E) {
        int dst = ei[E + e];
        int pos = atomicAdd(&g_cur[dst], 1);
        g_csr[pos] = ei[e];
    }
}

// ---------------- gather-sum + g + BN1 stats ----------------
__global__ void __launch_bounds__(256)
k_gather(const float* __restrict__ b, int n) {
    __shared__ float ss[8][128];
    __shared__ float sq[8][128];
    int tid = threadIdx.x;
    int warp = tid >> 5, lane = tid & 31;
    int c = lane * 4;
    int d = blockIdx.x * 8 + warp;

    float4 gv = make_float4(0.f, 0.f, 0.f, 0.f);
    if (d < n) {
        int st = g_offs[d];
        int ne = g_ecnt[d];
        float4 a0 = make_float4(0.f, 0.f, 0.f, 0.f);
        float4 a1 = make_float4(0.f, 0.f, 0.f, 0.f);
        float4 a2 = make_float4(0.f, 0.f, 0.f, 0.f);
        float4 a3 = make_float4(0.f, 0.f, 0.f, 0.f);
        int i = 0;
        for (; i + 4 <= ne; i += 4) {
            int sA = g_csr[st + i];
            int sB = g_csr[st + i + 1];
            int sC = g_csr[st + i + 2];
            int sD = g_csr[st + i + 3];
            float4 vA = *(const float4*)(g_hs + (size_t)sA * D + c);
            float4 vB = *(const float4*)(g_hs + (size_t)sB * D + c);
            float4 vC = *(const float4*)(g_hs + (size_t)sC * D + c);
            float4 vD = *(const float4*)(g_hs + (size_t)sD * D + c);
            a0.x += vA.x; a0.y += vA.y; a0.z += vA.z; a0.w += vA.w;
            a1.x += vB.x; a1.y += vB.y; a1.z += vB.z; a1.w += vB.w;
            a2.x += vC.x; a2.y += vC.y; a2.z += vC.z; a2.w += vC.w;
            a3.x += vD.x; a3.y += vD.y; a3.z += vD.z; a3.w += vD.w;
        }
        for (; i < ne; i++) {
            int sA = g_csr[st + i];
            float4 vA = *(const float4*)(g_hs + (size_t)sA * D + c);
            a0.x += vA.x; a0.y += vA.y; a0.z += vA.z; a0.w += vA.w;
        }
        float4 self = *(const float4*)(g_hs + (size_t)d * D + c);
        float dv = g_dinv[d];
        float4 bv = *(const float4*)(b + c);
        gv.x = dv * ((a0.x + a1.x) + (a2.x + a3.x) + self.x) + bv.x;
        gv.y = dv * ((a0.y + a1.y) + (a2.y + a3.y) + self.y) + bv.y;
        gv.z = dv * ((a0.z + a1.z) + (a2.z + a3.z) + self.z) + bv.z;
        gv.w = dv * ((a0.w + a1.w) + (a2.w + a3.w) + self.w) + bv.w;
        *(float4*)(g_acc + (size_t)d * D + c) = gv;
    }
    *(float4*)(&ss[warp][c]) = gv;
    *(float4*)(&sq[warp][c]) = make_float4(gv.x * gv.x, gv.y * gv.y, gv.z * gv.z, gv.w * gv.w);
    __syncthreads();
    if (tid < 128) {
        float s = 0.f, q = 0.f;
        #pragma unroll
        for (int w = 0; w < 8; w++) { s += ss[w][tid]; q += sq[w][tid]; }
        atomicAdd(&g_sum[tid], s);
        atomicAdd(&g_sq[tid], q);
    }
}

__global__ void k_finalize(const float* __restrict__ gamma, const float* __restrict__ beta,
                           int stage, float invn) {
    int i = threadIdx.x;
    if (i < D) {
        float m = g_sum[stage * D + i] * invn;
        float q = g_sq[stage * D + i] * invn;
        float var = q - m * m;
        float sc = gamma[i] * rsqrtf(var + 1e-5f);
        g_scale[stage * D + i] = sc;
        g_shift[stage * D + i] = beta[i] - m * sc;
    }
}

// r = x + relu(bn1(g)) -> stored into g_hs; accumulate BN2 stats
__global__ void k_r(const float* __restrict__ x, int n) {
    __shared__ float sm[512];
    int tid = threadIdx.x;
    int col = tid & (D - 1);
    int half = tid >> 7;
    int row0 = blockIdx.x * 256;
    float sc = g_scale[col];
    float sh = g_shift[col];
    float sum = 0.f, sq = 0.f;
    for (int rr = 0; rr < 128; rr++) {
        int row = row0 + rr * 2 + half;
        if (row < n) {
            size_t idx = (size_t)row * D + col;
            float g = g_acc[idx];
            float v = fmaxf(fmaf(g, sc, sh), 0.f);
            float r = x[idx] + v;
            g_hs[idx] = r;
            sum += r; sq += r * r;
        }
    }
    sm[tid] = sum; sm[256 + tid] = sq;
    __syncthreads();
    if (tid < 128) {
        float s = sm[tid] + sm[tid + 128];
        float q = sm[256 + tid] + sm[256 + tid + 128];
        atomicAdd(&g_sum[D + tid], s);
        atomicAdd(&g_sq[D + tid], q);
    }
}

// BN3 stats over y (= g_acc)
__global__ void k_ystats(int n) {
    __shared__ float sm[512];
    int tid = threadIdx.x;
    int col = tid & (D - 1);
    int half = tid >> 7;
    int row0 = blockIdx.x * 256;
    float sum = 0.f, sq = 0.f;
    for (int rr = 0; rr < 128; rr++) {
        int row = row0 + rr * 2 + half;
        if (row < n) {
            float y = g_acc[(size_t)row * D + col];
            sum += y; sq += y * y;
        }
    }
    sm[tid] = sum; sm[256 + tid] = sq;
    __syncthreads();
    if (tid < 128) {
        float s = sm[tid] + sm[tid + 128];
        float q = sm[256 + tid] + sm[256 + tid + 128];
        atomicAdd(&g_sum[2 * D + tid], s);
        atomicAdd(&g_sq[2 * D + tid], q);
    }
}

__global__ void k_out(float* __restrict__ out, int n) {
    int i = blockIdx.x * blockDim.x + threadIdx.x;
    int total = n * 32;
    if (i < total) {
        int c4 = (i & 31) * 4;
        float4 v = *(const float4*)(g_acc + (size_t)i * 4);
        float4 s = *(const float4*)(g_scale + 2 * D + c4);
        float4 h = *(const float4*)(g_shift + 2 * D + c4);
        float4 o;
        o.x = fmaf(v.x, s.x, h.x);
        o.y = fmaf(v.y, s.y, h.y);
        o.z = fmaf(v.z, s.z, h.z);
        o.w = fmaf(v.w, s.w, h.w);
        *(float4*)(out + (size_t)i * 4) = o;
    }
}

// ---------------- bf16x3 mma.sync GEMM (128x128 tile, 8 warps, 2 CTAs/SM) ----------------
// B-registers halved: per ks step, g-pairs {0,1} then {2,3} are loaded and consumed,
// capping live regs ~116 so __launch_bounds__(256,2) fits without spills.
// MODE 0: hs = (x @ W) * dinv[row]                   (A=x,  K=128, out cols 128)
// MODE 1: z  = relu((r*sc2+sh2) @ W1 + b1)           (A=hs, K=128, out cols 256 via grid.y)
// MODE 2: y  = z @ W2 + b2 + bn2(r)                  (A=z,  K=256, out cols 128)
template<int MODE, int KTOT>
__global__ void __launch_bounds__(256, 2)
k_mgemm(const float* __restrict__ Ain, const float* __restrict__ Wg,
        const float* __restrict__ bias, int M) {
    constexpr int LDW = (MODE == 1) ? 256 : 128;   // W row stride (floats)
    constexpr int LDO = (MODE == 1) ? 256 : 128;   // output row stride
    constexpr int AH = 0, AL = 16384, BH = 32768, BL = 49152;

    extern __shared__ char smem[];
    uint32_t sb = smem_u32(smem);
    int tid = threadIdx.x;
    int wid = tid >> 5;
    int lane = tid & 31;
    int warp_m = wid >> 1;          // 0..3 (32 rows each)
    int warp_n = wid & 1;           // 0..1 (64 cols each)
    int rowBase = blockIdx.x * 128;
    int colBase = blockIdx.y * 128; // only MODE 1 has grid.y = 2

    const float* A = (MODE == 0) ? Ain : (MODE == 1 ? g_hs : g_z);

    float acc[2][8][4];
    #pragma unroll
    for (int mt = 0; mt < 2; mt++)
        #pragma unroll
        for (int j = 0; j < 8; j++)
            #pragma unroll
            for (int q = 0; q < 4; q++) acc[mt][j][q] = 0.f;

    for (int kt = 0; kt < KTOT / 64; kt++) {
        if (kt > 0) __syncthreads();
        // ---- stage A chunk [128 rows x 64 k] -> hi/lo bf16 planes ----
        #pragma unroll
        for (int it = 0; it < 4; it++) {
            int u = it * 256 + tid;          // 1024 16B units
            int r = u >> 3, c16 = u & 7;
            int gr = rowBase + r;
            int kk = kt * 64 + c16 * 8;
            float4 v0 = make_float4(0.f, 0.f, 0.f, 0.f), v1 = v0;
            if (gr < M) {
                const float* ap = A + (size_t)gr * KTOT + kk;
                v0 = *(const float4*)(ap);
                v1 = *(const float4*)(ap + 4);
            }
            if (MODE == 1) {
                float4 s0 = *(const float4*)(g_scale + D + kk);
                float4 s1 = *(const float4*)(g_scale + D + kk + 4);
                float4 h0 = *(const float4*)(g_shift + D + kk);
                float4 h1 = *(const float4*)(g_shift + D + kk + 4);
                v0.x = fmaf(v0.x, s0.x, h0.x); v0.y = fmaf(v0.y, s0.y, h0.y);
                v0.z = fmaf(v0.z, s0.z, h0.z); v0.w = fmaf(v0.w, s0.w, h0.w);
                v1.x = fmaf(v1.x, s1.x, h1.x); v1.y = fmaf(v1.y, s1.y, h1.y);
                v1.z = fmaf(v1.z, s1.z, h1.z); v1.w = fmaf(v1.w, s1.w, h1.w);
            }
            uint4 hiU, loU;
            split2(v0.x, v0.y, hiU.x, loU.x);
            split2(v0.z, v0.w, hiU.y, loU.y);
            split2(v1.x, v1.y, hiU.z, loU.z);
            split2(v1.z, v1.w, hiU.w, loU.w);
            int ofs = (r * 8 + (c16 ^ (r & 7))) * 16;
            *(uint4*)(smem + AH + ofs) = hiU;
            *(uint4*)(smem + AL + ofs) = loU;
        }
        // ---- stage B chunk: W[kt*64..+64][colBase..+128] -> hi/lo planes ----
        #pragma unroll
        for (int it = 0; it < 4; it++) {
            int u = it * 256 + tid;
            int k = u >> 4, c16 = u & 15;
            int gk = kt * 64 + k;
            const float* wp = Wg + (size_t)gk * LDW + colBase + c16 * 8;
            float4 v0 = *(const float4*)(wp);
            float4 v1 = *(const float4*)(wp + 4);
            uint4 hiU, loU;
            split2(v0.x, v0.y, hiU.x, loU.x);
            split2(v0.z, v0.w, hiU.y, loU.y);
            split2(v1.x, v1.y, hiU.z, loU.z);
            split2(v1.z, v1.w, hiU.w, loU.w);
            int ofs = (k * 16 + (c16 ^ (k & 7))) * 16;
            *(uint4*)(smem + BH + ofs) = hiU;
            *(uint4*)(smem + BL + ofs) = loU;
        }
        __syncthreads();
        // ---- compute 4 k16-steps; B loaded in two g-pair passes ----
        #pragma unroll
        for (int ks = 0; ks < 4; ks++) {
            uint32_t ah[2][4], al[2][4];
            #pragma unroll
            for (int mt = 0; mt < 2; mt++) {
                int r = warp_m * 32 + mt * 16 + (lane & 15);
                int c16 = ks * 2 + (lane >> 4);
                uint32_t ad = sb + AH + (uint32_t)((r * 8 + (c16 ^ (r & 7))) * 16);
                ldsm_x4(ah[mt], ad);
                ldsm_x4(al[mt], ad + 16384);
            }
            #pragma unroll
            for (int gp = 0; gp < 2; gp++) {
                uint32_t bh[2][4], bl[2][4];
                #pragma unroll
                for (int gg = 0; gg < 2; gg++) {
                    int g = gp * 2 + gg;
                    int k = ks * 16 + (lane & 15);
                    int c16 = warp_n * 8 + g * 2 + (lane >> 4);
                    uint32_t bd = sb + BH + (uint32_t)((k * 16 + (c16 ^ (k & 7))) * 16);
                    ldsm_x4_t(bh[gg], bd);
                    ldsm_x4_t(bl[gg], bd + 16384);
                }
                #pragma unroll
                for (int mt = 0; mt < 2; mt++)
                    #pragma unroll
                    for (int jj = 0; jj < 4; jj++) {
                        int j = gp * 4 + jj;
                        int gg = jj >> 1, s = (jj & 1) * 2;
                        mma16816(acc[mt][j], ah[mt], bh[gg][s], bh[gg][s + 1]);
                        mma16816(acc[mt][j], ah[mt], bl[gg][s], bl[gg][s + 1]);
                        mma16816(acc[mt][j], al[mt], bh[gg][s], bh[gg][s + 1]);
                    }
            }
        }
    }

    // ---- epilogue ----
    int lane4 = lane >> 2;
    int lane2 = (lane & 3) * 2;
    #pragma unroll
    for (int mt = 0; mt < 2; mt++) {
        int r0 = rowBase + warp_m * 32 + mt * 16 + lane4;   // and r0+8
        #pragma unroll
        for (int j = 0; j < 8; j++) {
            int gc = colBase + warp_n * 64 + j * 8 + lane2;
            float c0 = acc[mt][j][0], c1 = acc[mt][j][1];
            float c2 = acc[mt][j][2], c3 = acc[mt][j][3];
            if (MODE == 0) {
                if (r0 < M) {
                    float dv = g_dinv[r0];
                    *(float2*)(g_hs + (size_t)r0 * LDO + gc) = make_float2(c0 * dv, c1 * dv);
                }
                if (r0 + 8 < M) {
                    float dv = g_dinv[r0 + 8];
                    *(float2*)(g_hs + (size_t)(r0 + 8) * LDO + gc) = make_float2(c2 * dv, c3 * dv);
                }
            } else if (MODE == 1) {
                float2 bv = *(const float2*)(bias + gc);
                if (r0 < M)
                    *(float2*)(g_z + (size_t)r0 * LDO + gc) =
                        make_float2(fmaxf(c0 + bv.x, 0.f), fmaxf(c1 + bv.y, 0.f));
                if (r0 + 8 < M)
                    *(float2*)(g_z + (size_t)(r0 + 8) * LDO + gc) =
                        make_float2(fmaxf(c2 + bv.x, 0.f), fmaxf(c3 + bv.y, 0.f));
            } else {
                float2 bv = *(const float2*)(bias + gc);
                float2 sc = *(const float2*)(g_scale + D + gc);
                float2 sh = *(const float2*)(g_shift + D + gc);
                if (r0 < M) {
                    float2 rv = *(const float2*)(g_hs + (size_t)r0 * 128 + gc);
                    float y0 = c0 + bv.x + fmaf(rv.x, sc.x, sh.x);
                    float y1 = c1 + bv.y + fmaf(rv.y, sc.y, sh.y);
                    *(float2*)(g_acc + (size_t)r0 * LDO + gc) = make_float2(y0, y1);
                }
                if (r0 + 8 < M) {
                    float2 rv = *(const float2*)(g_hs + (size_t)(r0 + 8) * 128 + gc);
                    float y2 = c2 + bv.x + fmaf(rv.x, sc.x, sh.x);
                    float y3 = c3 + bv.y + fmaf(rv.y, sc.y, sh.y);
                    *(float2*)(g_acc + (size_t)(r0 + 8) * LDO + gc) = make_float2(y2, y3);
                }
            }
        }
    }
}

// ---------------- launch ----------------
extern "C" void kernel_launch(void* const* d_in, const int* in_sizes, int n_in,
                              void* d_out, int out_size) {
    const float* x      = (const float*)d_in[0];
    const int*   ei     = (const int*)  d_in[1];
    const float* W      = (const float*)d_in[2];
    const float* b      = (const float*)d_in[3];
    const float* gamma1 = (const float*)d_in[4];
    const float* beta1  = (const float*)d_in[5];
    const float* gamma2 = (const float*)d_in[6];
    const float* beta2  = (const float*)d_in[7];
    const float* gamma3 = (const float*)d_in[8];
    const float* beta3  = (const float*)d_in[9];
    const float* W1     = (const float*)d_in[10];
    const float* b1     = (const float*)d_in[11];
    const float* W2     = (const float*)d_in[12];
    const float* b2     = (const float*)d_in[13];
    float* out = (float*)d_out;

    int N = in_sizes[0] / D;
    int E = in_sizes[1] / 2;
    float invn = 1.0f / (float)N;

    int smemB = 65536;
    cudaFuncSetAttribute(k_mgemm<0, 128>, cudaFuncAttributeMaxDynamicSharedMemorySize, smemB);
    cudaFuncSetAttribute(k_mgemm<1, 128>, cudaFuncAttributeMaxDynamicSharedMemorySize, smemB);
    cudaFuncSetAttribute(k_mgemm<2, 256>, cudaFuncAttributeMaxDynamicSharedMemorySize, smemB);

    void *p_ecnt, *p_sum, *p_sq;
    cudaGetSymbolAddress(&p_ecnt, g_ecnt);
    cudaGetSymbolAddress(&p_sum, g_sum);
    cudaGetSymbolAddress(&p_sq, g_sq);

    int gb = (N + 127) / 128;
    int sblocks = (N + 1023) / 1024;

    cudaMemsetAsync(p_ecnt, 0, (size_t)N * sizeof(int), 0);
    cudaMemsetAsync(p_sum, 0, 3 * D * sizeof(float), 0);
    cudaMemsetAsync(p_sq, 0, 3 * D * sizeof(float), 0);
    k_count<<<(E + 255) / 256, 256>>>(ei, E);
    k_scan1<<<sblocks, 1024>>>(N);
    k_scan2<<<1, 128>>>(sblocks);
    k_scan3<<<sblocks, 1024>>>(N);
    k_bucket<<<(E + 255) / 256, 256>>>(ei, E);
    k_mgemm<0, 128><<<gb, 256, smemB>>>(x, W, (const float*)0, N);
    k_gather<<<(N + 7) / 8, 256>>>(b, N);
    k_finalize<<<1, 128>>>(gamma1, beta1, 0, invn);
    k_r<<<(N + 255) / 256, 256>>>(x, N);
    k_finalize<<<1, 128>>>(gamma2, beta2, 1, invn);
    k_mgemm<1, 128><<<dim3(gb, 2), 256, smemB>>>((const float*)0, W1, b1, N);
    k_mgemm<2, 256><<<gb, 256, smemB>>>((const float*)0, W2, b2, N);
    k_ystats<<<(N + 255) / 256, 256>>>(N);
    k_finalize<<<1, 128>>>(gamma3, beta3, 2, invn);
    k_out<<<(N * 32 + 255) / 256, 256>>>(out, N);
}